// round 16
// baseline (speedup 1.0000x reference)
#include <cuda_runtime.h>
#include <cuda_bf16.h>
#include <mma.h>

using namespace nvcuda;
typedef unsigned int uint32;

// ---------------- scratch (device globals: allocation-free rule) -------------
__device__ __nv_bfloat16 g_qkvh[(size_t)4096 * 64 * 288];  // bf16 qkv
__device__ float g_x2[(size_t)64 * 4096 * 96];             // x + attn branch
__device__ __nv_bfloat16 g_qwh[27648];
__device__ __nv_bfloat16 g_pwh[9216];
__device__ __nv_bfloat16 g_w1h[36864];
__device__ __nv_bfloat16 g_w2h[36864];

// =============================================================================
// K0: one-shot weight conversion fp32 -> bf16 (runs every replay; ~10us)
// =============================================================================
__global__ void k0_cvt_weights(const float* __restrict__ qw, const float* __restrict__ pw,
                               const float* __restrict__ w1, const float* __restrict__ w2)
{
    int i = blockIdx.x * 256 + threadIdx.x;
    if (i < 27648) g_qwh[i] = __float2bfloat16(qw[i]);
    if (i < 9216)  g_pwh[i] = __float2bfloat16(pw[i]);
    if (i < 36864) { g_w1h[i] = __float2bfloat16(w1[i]); g_w2h[i] = __float2bfloat16(w2[i]); }
}

// =============================================================================
// K1: LN1 + shift + window partition + QKV GEMM (wmma bf16) -> g_qkvh (bf16)
// 256 thr / 8 warps; CTA = 128 tokens = 2 windows (grid 2048). smem 99840 B.
// =============================================================================
__global__ void __launch_bounds__(256) k1_ln_qkv_tc(
    const float* __restrict__ x, const float* __restrict__ g1,
    const float* __restrict__ b1, const float* __restrict__ qb)
{
    extern __shared__ char smraw[];
    __nv_bfloat16* A  = reinterpret_cast<__nv_bfloat16*>(smraw);          // [128][104]
    __nv_bfloat16* Wc = reinterpret_cast<__nv_bfloat16*>(smraw + 26624);  // [96][104]
    float*         C  = reinterpret_cast<float*>(smraw + 46592);          // [128][104]

    const int tid = threadIdx.x;
    const int warp = tid >> 5;

    {   // ---- LN1 + shift + gather: 2 lanes per token, 48 ch each ----
        int t = tid >> 1, part = tid & 1;
        int wh = t >> 6;
        int wnd = (blockIdx.x << 1) + wh;
        int b = wnd >> 6, wy = (wnd >> 3) & 7, wx = wnd & 7;
        int tl = t & 63;
        int ty = tl >> 3, tx = tl & 7;
        int y0 = ((wy << 3) + ty + 4) & 63;
        int x0 = ((wx << 3) + tx + 4) & 63;
        const float4* src = reinterpret_cast<const float4*>(
            x + ((size_t)((b << 12) + (y0 << 6) + x0)) * 96 + part * 48);
        float v[48]; float s = 0.f, s2 = 0.f;
        #pragma unroll
        for (int i = 0; i < 12; i++) {
            float4 f = src[i];
            v[4*i] = f.x; v[4*i+1] = f.y; v[4*i+2] = f.z; v[4*i+3] = f.w;
        }
        #pragma unroll
        for (int i = 0; i < 48; i++) { s += v[i]; s2 += v[i] * v[i]; }
        s  += __shfl_xor_sync(0xffffffffu, s, 1);
        s2 += __shfl_xor_sync(0xffffffffu, s2, 1);
        float mu   = s * (1.f / 96.f);
        float rstd = rsqrtf(s2 * (1.f / 96.f) - mu * mu + 1e-5f);
        #pragma unroll
        for (int i = 0; i < 48; i++) {
            int c = part * 48 + i;
            A[t * 104 + c] = __float2bfloat16((v[i] - mu) * rstd * g1[c] + b1[c]);
        }
    }

    uint32* Wc_u = reinterpret_cast<uint32*>(Wc);
    const uint32* qwh_u = reinterpret_cast<const uint32*>(g_qwh);
    uint32* dst_u = reinterpret_cast<uint32*>(g_qkvh);

    for (int ch = 0; ch < 3; ch++) {
        // ---- stage bf16 weight chunk [96 out][96 k] via u32 ----
        for (int idx = tid; idx < 4608; idx += 256) {
            int o = idx / 48, kp = idx - o * 48;
            Wc_u[o * 52 + kp] = qwh_u[(ch * 96 + o) * 48 + kp];
        }
        __syncthreads();

        wmma::fragment<wmma::accumulator, 16, 16, 16, float> cf[6];
        #pragma unroll
        for (int nn = 0; nn < 6; nn++) wmma::fill_fragment(cf[nn], 0.f);
        #pragma unroll
        for (int kk = 0; kk < 6; kk++) {
            wmma::fragment<wmma::matrix_a, 16, 16, 16, __nv_bfloat16, wmma::row_major> af;
            wmma::load_matrix_sync(af, A + warp * 16 * 104 + kk * 16, 104);
            #pragma unroll
            for (int nn = 0; nn < 6; nn++) {
                wmma::fragment<wmma::matrix_b, 16, 16, 16, __nv_bfloat16, wmma::col_major> bf;
                wmma::load_matrix_sync(bf, Wc + nn * 16 * 104 + kk * 16, 104);
                wmma::mma_sync(cf[nn], af, bf, cf[nn]);
            }
        }
        #pragma unroll
        for (int nn = 0; nn < 6; nn++)
            wmma::store_matrix_sync(C + warp * 16 * 104 + nn * 16, cf[nn], 104,
                                    wmma::mem_row_major);
        __syncthreads();

        // ---- epilogue: bias (+q scale) -> bf16 pair stores ----
        const float sc = (ch == 0) ? 0.20412414523193154f : 1.f;
        for (int idx = tid; idx < 6144; idx += 256) {
            int t2 = idx / 48, op = idx - t2 * 48;
            float lo = (C[t2 * 104 + 2 * op]     + qb[ch * 96 + 2 * op])     * sc;
            float hi = (C[t2 * 104 + 2 * op + 1] + qb[ch * 96 + 2 * op + 1]) * sc;
            __nv_bfloat162 v2 = __floats2bfloat162_rn(lo, hi);
            int wnd2 = (blockIdx.x << 1) + (t2 >> 6), row = t2 & 63;
            dst_u[((size_t)wnd2 * 64 + row) * 144 + ch * 48 + op] =
                *reinterpret_cast<uint32*>(&v2);
        }
        __syncthreads();
    }
}

// =============================================================================
// K2: windowed attention FULLY on tensor cores + proj + residual -> g_x2
// 256 thr / 8 warps = ONE window (grid 4096). QK^T, PV, proj via wmma bf16.
// Max-free softmax fp32 in registers. smem 188432 B -> 1 CTA/SM.
// =============================================================================
__global__ void __launch_bounds__(256) k2_attn_tc(
    const float* __restrict__ x, const float* __restrict__ btab,
    const float* __restrict__ pb)
{
    extern __shared__ char smraw[];
    __nv_bfloat16* Qs  = reinterpret_cast<__nv_bfloat16*>(smraw);           // [4][64][32]
    __nv_bfloat16* Ks  = reinterpret_cast<__nv_bfloat16*>(smraw + 16384);   // [4][64][32]
    __nv_bfloat16* Vs  = reinterpret_cast<__nv_bfloat16*>(smraw + 32768);   // [4][64][32]
    float*         Ssm = reinterpret_cast<float*>(smraw + 49152);           // [4][64][68]
    __nv_bfloat16* P   = reinterpret_cast<__nv_bfloat16*>(smraw + 118784);  // [4][64][64]
    __nv_bfloat16* AO  = reinterpret_cast<__nv_bfloat16*>(smraw + 151552);  // [64][104]
    __nv_bfloat16* pws = reinterpret_cast<__nv_bfloat16*>(smraw + 164864);  // [96][104]
    float*         bsm = reinterpret_cast<float*>(smraw + 184832);          // [900]

    const int tid = threadIdx.x, warp = tid >> 5;
    const int wnd = blockIdx.x;
    const int b = wnd >> 6, wy = (wnd >> 3) & 7, wx = wnd & 7;
    const uint32* qkvh_u = reinterpret_cast<const uint32*>(g_qkvh) + (size_t)wnd * 64 * 144;

    // ---- stage Q/K/V bf16 (u32 pairs) + zero k-pad ----
    uint32* Qu = reinterpret_cast<uint32*>(Qs);
    uint32* Ku = reinterpret_cast<uint32*>(Ks);
    uint32* Vu = reinterpret_cast<uint32*>(Vs);
    for (int e = tid; e < 9216; e += 256) {
        int arr = e / 3072, r = e - arr * 3072;
        int h2 = r / 768, r2 = r - h2 * 768;
        int tok = r2 / 12, kp = r2 - tok * 12;
        uint32 v = qkvh_u[tok * 144 + arr * 48 + h2 * 12 + kp];
        uint32* dst = (arr == 0) ? Qu : ((arr == 1) ? Ku : Vu);
        dst[h2 * 1024 + tok * 16 + kp] = v;
    }
    for (int e = tid; e < 3072; e += 256) {
        int arr = e >> 10, r = e & 1023;
        int h2 = r >> 8, r2 = r & 255, tok = r2 >> 2, kp = 12 + (r2 & 3);
        uint32* dst = (arr == 0) ? Qu : ((arr == 1) ? Ku : Vu);
        dst[h2 * 1024 + tok * 16 + kp] = 0u;
    }
    {   // proj weights + bias table
        uint32* pws_u = reinterpret_cast<uint32*>(pws);
        const uint32* pwh_u = reinterpret_cast<const uint32*>(g_pwh);
        for (int idx = tid; idx < 4608; idx += 256) {
            int o = idx / 48, kp = idx - o * 48;
            pws_u[o * 52 + kp] = pwh_u[o * 48 + kp];
        }
        for (int e = tid; e < 900; e += 256) bsm[e] = btab[e];
    }
    __syncthreads();

    // ---- S = Q K^T (warp = (head, row-half)) ----
    {
        int h = warp >> 1, mh = warp & 1;
        wmma::fragment<wmma::accumulator, 16, 16, 16, float> sacc[2][4];
        #pragma unroll
        for (int mt = 0; mt < 2; mt++)
            #pragma unroll
            for (int nt = 0; nt < 4; nt++) wmma::fill_fragment(sacc[mt][nt], 0.f);
        #pragma unroll
        for (int kk = 0; kk < 2; kk++) {
            wmma::fragment<wmma::matrix_a, 16, 16, 16, __nv_bfloat16, wmma::row_major> af[2];
            #pragma unroll
            for (int mt = 0; mt < 2; mt++)
                wmma::load_matrix_sync(af[mt],
                    Qs + h * 2048 + (mh * 32 + mt * 16) * 32 + kk * 16, 32);
            #pragma unroll
            for (int nt = 0; nt < 4; nt++) {
                wmma::fragment<wmma::matrix_b, 16, 16, 16, __nv_bfloat16, wmma::col_major> bf;
                wmma::load_matrix_sync(bf, Ks + h * 2048 + nt * 16 * 32 + kk * 16, 32);
                #pragma unroll
                for (int mt = 0; mt < 2; mt++)
                    wmma::mma_sync(sacc[mt][nt], af[mt], bf, sacc[mt][nt]);
            }
        }
        #pragma unroll
        for (int mt = 0; mt < 2; mt++)
            #pragma unroll
            for (int nt = 0; nt < 4; nt++)
                wmma::store_matrix_sync(
                    Ssm + h * 4352 + (mh * 32 + mt * 16) * 68 + nt * 16,
                    sacc[mt][nt], 68, wmma::mem_row_major);
    }
    __syncthreads();

    // ---- softmax (max-free; scores tiny) thread = (h, i) ----
    {
        int h = tid >> 6, i = tid & 63;
        int iy = i >> 3, ix = i & 7;
        int cx = (wx == 7) ? ((ix < 4) ? 1 : 2) : 0;
        int cy = (wy == 7) ? ((iy < 4) ? 1 : 2) : 0;
        int cnti = cy * 3 + cx;
        const float* Srow = Ssm + h * 4352 + i * 68;
        float ev[64]; float sum = 0.f;
        #pragma unroll
        for (int j = 0; j < 64; j++) {
            int jy = j >> 3, jx = j & 7;
            float bias = bsm[((iy - jy + 7) * 15 + (ix - jx + 7)) * 4 + h];
            int cntj = ((wy == 7) ? ((jy < 4) ? 1 : 2) : 0) * 3
                     + ((wx == 7) ? ((jx < 4) ? 1 : 2) : 0);
            float m = (cnti != cntj) ? -100.f : 0.f;
            float e = __expf(Srow[j] + bias + m);
            ev[j] = e; sum += e;
        }
        float inv = 1.f / sum;
        uint32* Prow = reinterpret_cast<uint32*>(P + h * 4096 + i * 64);
        #pragma unroll
        for (int jp = 0; jp < 32; jp++) {
            __nv_bfloat162 v2 = __floats2bfloat162_rn(ev[2*jp] * inv, ev[2*jp+1] * inv);
            Prow[jp] = *reinterpret_cast<uint32*>(&v2);
        }
    }
    __syncthreads();

    // ---- O = P V  (overwrites Ssm) ----
    {
        int h = warp >> 1, mh = warp & 1;
        wmma::fragment<wmma::accumulator, 16, 16, 16, float> oacc[2][2];
        #pragma unroll
        for (int mt = 0; mt < 2; mt++)
            #pragma unroll
            for (int nt = 0; nt < 2; nt++) wmma::fill_fragment(oacc[mt][nt], 0.f);
        #pragma unroll
        for (int kk = 0; kk < 4; kk++) {
            wmma::fragment<wmma::matrix_a, 16, 16, 16, __nv_bfloat16, wmma::row_major> af[2];
            #pragma unroll
            for (int mt = 0; mt < 2; mt++)
                wmma::load_matrix_sync(af[mt],
                    P + h * 4096 + (mh * 32 + mt * 16) * 64 + kk * 16, 64);
            #pragma unroll
            for (int nt = 0; nt < 2; nt++) {
                wmma::fragment<wmma::matrix_b, 16, 16, 16, __nv_bfloat16, wmma::row_major> bf;
                wmma::load_matrix_sync(bf, Vs + h * 2048 + kk * 16 * 32 + nt * 16, 32);
                #pragma unroll
                for (int mt = 0; mt < 2; mt++)
                    wmma::mma_sync(oacc[mt][nt], af[mt], bf, oacc[mt][nt]);
            }
        }
        #pragma unroll
        for (int mt = 0; mt < 2; mt++)
            #pragma unroll
            for (int nt = 0; nt < 2; nt++)
                wmma::store_matrix_sync(
                    Ssm + h * 4352 + (mh * 32 + mt * 16) * 68 + nt * 16,
                    oacc[mt][nt], 68, wmma::mem_row_major);
    }
    __syncthreads();

    // ---- O -> bf16 AO [64][104] (concat heads) ----
    {
        int h = tid >> 6, row = tid & 63;
        const float* orow = Ssm + h * 4352 + row * 68;
        #pragma unroll
        for (int cc = 0; cc < 24; cc++)
            AO[row * 104 + h * 24 + cc] = __float2bfloat16(orow[cc]);
    }
    __syncthreads();

    // ---- proj: Cp[64][96] = AO x pws^T (Cp reuses Ssm) ----
    {
        int mt = warp & 3, nb = (warp >> 2) * 3;
        wmma::fragment<wmma::accumulator, 16, 16, 16, float> pacc[3];
        #pragma unroll
        for (int ni = 0; ni < 3; ni++) wmma::fill_fragment(pacc[ni], 0.f);
        #pragma unroll
        for (int kk = 0; kk < 6; kk++) {
            wmma::fragment<wmma::matrix_a, 16, 16, 16, __nv_bfloat16, wmma::row_major> af;
            wmma::load_matrix_sync(af, AO + mt * 16 * 104 + kk * 16, 104);
            #pragma unroll
            for (int ni = 0; ni < 3; ni++) {
                wmma::fragment<wmma::matrix_b, 16, 16, 16, __nv_bfloat16, wmma::col_major> bf;
                wmma::load_matrix_sync(bf, pws + (nb + ni) * 16 * 104 + kk * 16, 104);
                wmma::mma_sync(pacc[ni], af, bf, pacc[ni]);
            }
        }
        float* Cp = Ssm;
        #pragma unroll
        for (int ni = 0; ni < 3; ni++)
            wmma::store_matrix_sync(Cp + mt * 16 * 104 + (nb + ni) * 16,
                                    pacc[ni], 104, wmma::mem_row_major);
    }
    __syncthreads();

    // ---- epilogue: reverse+unshift + residual -> g_x2 ----
    {
        const float* Cp = Ssm;
        for (int idx = tid; idx < 6144; idx += 256) {
            int row = idx / 96, o = idx - row * 96;
            int ty = row >> 3, tx = row & 7;
            int y0 = ((wy << 3) + ty + 4) & 63;
            int x0 = ((wx << 3) + tx + 4) & 63;
            size_t g = ((size_t)((b << 12) + (y0 << 6) + x0)) * 96 + o;
            g_x2[g] = x[g] + Cp[row * 104 + o] + pb[o];
        }
    }
}

// =============================================================================
// K3: LN2 + fc1 + exact GELU + fc2 + residual -> out  (wmma bf16; bf16 weights)
// 256 thr / 8 warps; CTA = 128 tokens (grid 2048). smem 109056 B.
// =============================================================================
__global__ void __launch_bounds__(256) k3_mlp_tc(
    const float* __restrict__ g2, const float* __restrict__ b2,
    const float* __restrict__ fb1, const float* __restrict__ fb2,
    float* __restrict__ out)
{
    extern __shared__ char smraw[];
    __nv_bfloat16* A   = reinterpret_cast<__nv_bfloat16*>(smraw);           // [128][104]
    float*         C1  = reinterpret_cast<float*>(smraw + 26624);           // [128][72]
    __nv_bfloat16* A2  = reinterpret_cast<__nv_bfloat16*>(smraw + 63488);   // [128][72]
    __nv_bfloat16* W1c = reinterpret_cast<__nv_bfloat16*>(smraw + 81920);   // [64][104]
    __nv_bfloat16* W2c = reinterpret_cast<__nv_bfloat16*>(smraw + 95232);   // [96][72]
    float*         C2s = reinterpret_cast<float*>(smraw);                   // [128][104] (reuse)

    const int tid = threadIdx.x;
    const int warp = tid >> 5;
    const size_t base = (size_t)blockIdx.x * 128 * 96;

    {   // ---- LN2 -> bf16 A ----
        int t = tid >> 1, part = tid & 1;
        const float4* src = reinterpret_cast<const float4*>(
            g_x2 + base + (size_t)t * 96 + part * 48);
        float v[48]; float s = 0.f, s2 = 0.f;
        #pragma unroll
        for (int i = 0; i < 12; i++) {
            float4 f = src[i];
            v[4*i] = f.x; v[4*i+1] = f.y; v[4*i+2] = f.z; v[4*i+3] = f.w;
        }
        #pragma unroll
        for (int i = 0; i < 48; i++) { s += v[i]; s2 += v[i] * v[i]; }
        s  += __shfl_xor_sync(0xffffffffu, s, 1);
        s2 += __shfl_xor_sync(0xffffffffu, s2, 1);
        float mu   = s * (1.f / 96.f);
        float rstd = rsqrtf(s2 * (1.f / 96.f) - mu * mu + 1e-5f);
        #pragma unroll
        for (int i = 0; i < 48; i++) {
            int c = part * 48 + i;
            A[t * 104 + c] = __float2bfloat16((v[i] - mu) * rstd * g2[c] + b2[c]);
        }
    }

    wmma::fragment<wmma::accumulator, 16, 16, 16, float> c2f[6];
    #pragma unroll
    for (int nn = 0; nn < 6; nn++) wmma::fill_fragment(c2f[nn], 0.f);

    uint32* W1u = reinterpret_cast<uint32*>(W1c);
    uint32* W2u = reinterpret_cast<uint32*>(W2c);
    const uint32* w1h_u = reinterpret_cast<const uint32*>(g_w1h);
    const uint32* w2h_u = reinterpret_cast<const uint32*>(g_w2h);

    for (int nch = 0; nch < 6; nch++) {
        __syncthreads();
        for (int idx = tid; idx < 3072; idx += 256) {        // w1 chunk [64][96]
            int nl = idx / 48, kp = idx - nl * 48;
            W1u[nl * 52 + kp] = w1h_u[(nch * 64 + nl) * 48 + kp];
        }
        for (int idx = tid; idx < 3072; idx += 256) {        // w2 chunk [96][64]
            int nl = idx >> 5, kp = idx & 31;
            W2u[nl * 36 + kp] = w2h_u[nl * 192 + nch * 32 + kp];
        }
        __syncthreads();

        // ---- fc1 ----
        wmma::fragment<wmma::accumulator, 16, 16, 16, float> c1f[4];
        #pragma unroll
        for (int nn = 0; nn < 4; nn++) wmma::fill_fragment(c1f[nn], 0.f);
        #pragma unroll
        for (int kk = 0; kk < 6; kk++) {
            wmma::fragment<wmma::matrix_a, 16, 16, 16, __nv_bfloat16, wmma::row_major> af;
            wmma::load_matrix_sync(af, A + warp * 16 * 104 + kk * 16, 104);
            #pragma unroll
            for (int nn = 0; nn < 4; nn++) {
                wmma::fragment<wmma::matrix_b, 16, 16, 16, __nv_bfloat16, wmma::col_major> bf;
                wmma::load_matrix_sync(bf, W1c + nn * 16 * 104 + kk * 16, 104);
                wmma::mma_sync(c1f[nn], af, bf, c1f[nn]);
            }
        }
        #pragma unroll
        for (int nn = 0; nn < 4; nn++)
            wmma::store_matrix_sync(C1 + warp * 16 * 72 + nn * 16, c1f[nn], 72,
                                    wmma::mem_row_major);
        __syncthreads();

        // ---- bias + exact GELU -> bf16 A2 ----
        for (int idx = tid; idx < 128 * 64; idx += 256) {
            int t = idx >> 6, c = idx & 63;
            float v = C1[t * 72 + c] + fb1[nch * 64 + c];
            v = 0.5f * v * (1.f + erff(v * 0.70710678118654752f));
            A2[t * 72 + c] = __float2bfloat16(v);
        }
        __syncthreads();

        // ---- fc2 partial ----
        #pragma unroll
        for (int kk = 0; kk < 4; kk++) {
            wmma::fragment<wmma::matrix_a, 16, 16, 16, __nv_bfloat16, wmma::row_major> a2f;
            wmma::load_matrix_sync(a2f, A2 + warp * 16 * 72 + kk * 16, 72);
            #pragma unroll
            for (int nn = 0; nn < 6; nn++) {
                wmma::fragment<wmma::matrix_b, 16, 16, 16, __nv_bfloat16, wmma::col_major> b2f;
                wmma::load_matrix_sync(b2f, W2c + nn * 16 * 72 + kk * 16, 72);
                wmma::mma_sync(c2f[nn], a2f, b2f, c2f[nn]);
            }
        }
    }
    __syncthreads();

    #pragma unroll
    for (int nn = 0; nn < 6; nn++)
        wmma::store_matrix_sync(C2s + warp * 16 * 104 + nn * 16, c2f[nn], 104,
                                wmma::mem_row_major);
    __syncthreads();
    for (int idx = tid; idx < 128 * 96; idx += 256) {
        int t = idx / 96, c = idx - t * 96;
        out[base + idx] = g_x2[base + idx] + C2s[t * 104 + c] + fb2[c];
    }
}

// =============================================================================
extern "C" void kernel_launch(void* const* d_in, const int* in_sizes, int n_in,
                              void* d_out, int out_size)
{
    (void)in_sizes; (void)n_in; (void)out_size;
    const float* x   = (const float*)d_in[0];
    const float* n1g = (const float*)d_in[1];
    const float* n1b = (const float*)d_in[2];
    const float* qw  = (const float*)d_in[3];
    const float* qb  = (const float*)d_in[4];
    const float* bt  = (const float*)d_in[5];
    const float* pw  = (const float*)d_in[6];
    const float* pb  = (const float*)d_in[7];
    const float* n2g = (const float*)d_in[8];
    const float* n2b = (const float*)d_in[9];
    const float* w1  = (const float*)d_in[10];
    const float* fb1 = (const float*)d_in[11];
    const float* w2  = (const float*)d_in[12];
    const float* fb2 = (const float*)d_in[13];
    float* out = (float*)d_out;

    cudaFuncSetAttribute(k1_ln_qkv_tc, cudaFuncAttributeMaxDynamicSharedMemorySize,  99840);
    cudaFuncSetAttribute(k2_attn_tc,   cudaFuncAttributeMaxDynamicSharedMemorySize, 188432);
    cudaFuncSetAttribute(k3_mlp_tc,    cudaFuncAttributeMaxDynamicSharedMemorySize, 109056);

    k0_cvt_weights<<<144, 256>>>(qw, pw, w1, w2);
    k1_ln_qkv_tc<<<2048, 256,  99840>>>(x, n1g, n1b, qb);
    k2_attn_tc  <<<4096, 256, 188432>>>(x, bt, pb);
    k3_mlp_tc   <<<2048, 256, 109056>>>(n2g, n2b, fb1, fb2, out);
}

// round 17
// speedup vs baseline: 1.3339x; 1.3339x over previous
#include <cuda_runtime.h>
#include <cuda_bf16.h>
#include <mma.h>

using namespace nvcuda;
typedef unsigned long long ull_t;
typedef unsigned int uint32;

// ---------------- scratch (device globals: allocation-free rule) -------------
__device__ float g_qkv[(size_t)4096 * 64 * 288];   // fp32 qkv (for scalar K2)
__device__ float g_x2 [(size_t)64 * 4096 * 96];    // x + attn branch
__device__ __nv_bfloat16 g_qwh[27648];
__device__ __nv_bfloat16 g_w1h[36864];
__device__ __nv_bfloat16 g_w2h[36864];

// ---------------- packed f32x2 helpers (FFMA2 path) --------------------------
static __device__ __forceinline__ ull_t pk2(float lo, float hi) {
    ull_t d;
    asm("mov.b64 %0, {%1,%2};" : "=l"(d)
        : "r"(__float_as_uint(lo)), "r"(__float_as_uint(hi)));
    return d;
}
static __device__ __forceinline__ void up2(ull_t v, float& lo, float& hi) {
    unsigned a, b;
    asm("mov.b64 {%0,%1}, %2;" : "=r"(a), "=r"(b) : "l"(v));
    lo = __uint_as_float(a); hi = __uint_as_float(b);
}
static __device__ __forceinline__ void fma2(ull_t& acc, ull_t a, ull_t b) {
    asm("fma.rn.f32x2 %0, %1, %2, %0;" : "+l"(acc) : "l"(a), "l"(b));
}

// =============================================================================
// K0: one-shot weight conversion fp32 -> bf16 (~10us)
// =============================================================================
__global__ void k0_cvt_weights(const float* __restrict__ qw,
                               const float* __restrict__ w1,
                               const float* __restrict__ w2)
{
    int i = blockIdx.x * 256 + threadIdx.x;
    if (i < 27648) g_qwh[i] = __float2bfloat16(qw[i]);
    if (i < 36864) { g_w1h[i] = __float2bfloat16(w1[i]); g_w2h[i] = __float2bfloat16(w2[i]); }
}

// =============================================================================
// K1: LN1 + shift + window partition + QKV GEMM (wmma bf16, bf16 weights)
// 256 thr / 8 warps; CTA = 128 tokens = 2 windows (grid 2048). smem 99840 B.
// fp32 output to g_qkv (scalar K2 consumes it).
// =============================================================================
__global__ void __launch_bounds__(256) k1_ln_qkv_tc(
    const float* __restrict__ x, const float* __restrict__ g1,
    const float* __restrict__ b1, const float* __restrict__ qb)
{
    extern __shared__ char smraw[];
    __nv_bfloat16* A  = reinterpret_cast<__nv_bfloat16*>(smraw);          // [128][104]
    __nv_bfloat16* Wc = reinterpret_cast<__nv_bfloat16*>(smraw + 26624);  // [96][104]
    float*         C  = reinterpret_cast<float*>(smraw + 46592);          // [128][104]

    const int tid = threadIdx.x;
    const int warp = tid >> 5;

    {   // ---- LN1 + shift + gather: 2 lanes per token, 48 ch each ----
        int t = tid >> 1, part = tid & 1;
        int wh = t >> 6;
        int wnd = (blockIdx.x << 1) + wh;
        int b = wnd >> 6, wy = (wnd >> 3) & 7, wx = wnd & 7;
        int tl = t & 63;
        int ty = tl >> 3, tx = tl & 7;
        int y0 = ((wy << 3) + ty + 4) & 63;
        int x0 = ((wx << 3) + tx + 4) & 63;
        const float4* src = reinterpret_cast<const float4*>(
            x + ((size_t)((b << 12) + (y0 << 6) + x0)) * 96 + part * 48);
        float v[48]; float s = 0.f, s2 = 0.f;
        #pragma unroll
        for (int i = 0; i < 12; i++) {
            float4 f = src[i];
            v[4*i] = f.x; v[4*i+1] = f.y; v[4*i+2] = f.z; v[4*i+3] = f.w;
        }
        #pragma unroll
        for (int i = 0; i < 48; i++) { s += v[i]; s2 += v[i] * v[i]; }
        s  += __shfl_xor_sync(0xffffffffu, s, 1);
        s2 += __shfl_xor_sync(0xffffffffu, s2, 1);
        float mu   = s * (1.f / 96.f);
        float rstd = rsqrtf(s2 * (1.f / 96.f) - mu * mu + 1e-5f);
        #pragma unroll
        for (int i = 0; i < 48; i++) {
            int c = part * 48 + i;
            A[t * 104 + c] = __float2bfloat16((v[i] - mu) * rstd * g1[c] + b1[c]);
        }
    }

    uint32* Wc_u = reinterpret_cast<uint32*>(Wc);
    const uint32* qwh_u = reinterpret_cast<const uint32*>(g_qwh);

    for (int ch = 0; ch < 3; ch++) {
        // ---- stage bf16 weight chunk [96 out][96 k] via u32 ----
        for (int idx = tid; idx < 4608; idx += 256) {
            int o = idx / 48, kp = idx - o * 48;
            Wc_u[o * 52 + kp] = qwh_u[(ch * 96 + o) * 48 + kp];
        }
        __syncthreads();            // Wc ready (iter 0: also A ready)

        wmma::fragment<wmma::accumulator, 16, 16, 16, float> cf[6];
        #pragma unroll
        for (int nn = 0; nn < 6; nn++) wmma::fill_fragment(cf[nn], 0.f);
        #pragma unroll
        for (int kk = 0; kk < 6; kk++) {
            wmma::fragment<wmma::matrix_a, 16, 16, 16, __nv_bfloat16, wmma::row_major> af;
            wmma::load_matrix_sync(af, A + warp * 16 * 104 + kk * 16, 104);
            #pragma unroll
            for (int nn = 0; nn < 6; nn++) {
                wmma::fragment<wmma::matrix_b, 16, 16, 16, __nv_bfloat16, wmma::col_major> bf;
                wmma::load_matrix_sync(bf, Wc + nn * 16 * 104 + kk * 16, 104);
                wmma::mma_sync(cf[nn], af, bf, cf[nn]);
            }
        }
        #pragma unroll
        for (int nn = 0; nn < 6; nn++)
            wmma::store_matrix_sync(C + warp * 16 * 104 + nn * 16, cf[nn], 104,
                                    wmma::mem_row_major);
        __syncthreads();            // C ready

        // ---- epilogue: bias (+ q scale on chunk 0) -> g_qkv fp32 ----
        const float sc = (ch == 0) ? 0.20412414523193154f : 1.f;
        for (int idx = tid; idx < 128 * 96; idx += 256) {
            int t2 = idx / 96, o = idx - t2 * 96;
            int wnd2 = (blockIdx.x << 1) + (t2 >> 6);
            int row = t2 & 63;
            int oo = ch * 96 + o;
            g_qkv[((size_t)wnd2 * 64 + row) * 288 + oo] = (C[t2 * 104 + o] + qb[oo]) * sc;
        }
        __syncthreads();            // done with Wc / C before next chunk
    }
}

// =============================================================================
// K2: windowed attention (max-free softmax) + proj + residual -> g_x2
// 128 threads = ONE window (grid 4096). Thread owns rows (i, i+32) of a head.
// smem 114576 B -> 2 CTAs/SM.  (R15 version, unchanged)
// =============================================================================
__global__ void __launch_bounds__(128, 2) k2_attn_proj(
    const float* __restrict__ x, const float* __restrict__ btab,
    const float* __restrict__ pw, const float* __restrict__ pb)
{
    extern __shared__ float sm[];
    float* ksm = sm;                     // [4][64][24]
    float* vsm = sm + 6144;              // [4][64][24]
    float* aot = sm + 12288;             // [96][64]
    float* pws = sm + 18432;             // [96][97]
    float* bsm = sm + 27744;             // [900]

    const int tid = threadIdx.x, lane = tid & 31;
    const int wnd = blockIdx.x;
    const int b = wnd >> 6, wy = (wnd >> 3) & 7, wx = wnd & 7;
    const float* qkvbase = g_qkv + (size_t)wnd * 64 * 288;
    const int h = tid >> 5;

    // ---- stage K, V ----
    for (int e = tid; e < 3072; e += 128) {
        int m   = (e >= 1536) ? 1 : 0;
        int r   = e - m * 1536;
        int row = r / 6, f4 = r - row * 6;
        int hr = row >> 6, ir = row & 63;
        const float4* s_ = reinterpret_cast<const float4*>(
            qkvbase + ir * 288 + 96 + m * 96 + hr * 24 + f4 * 4);
        float* d_ = (m ? vsm : ksm) + row * 24 + f4 * 4;
        *reinterpret_cast<float4*>(d_) = *s_;
    }
    for (int e = tid; e < 9216; e += 128) {      // proj weights
        int o = e / 96, c = e - o * 96;
        pws[o * 97 + c] = pw[e];
    }
    for (int e = tid; e < 900; e += 128) bsm[e] = btab[e];

    // ---- q rows i0 = lane, i1 = lane+32 (pre-scaled in K1) ----
    const int i0 = lane, i1 = lane + 32;
    ull_t q2[24];
    {
        const float4* sq0 = reinterpret_cast<const float4*>(qkvbase + i0 * 288 + h * 24);
        const float4* sq1 = reinterpret_cast<const float4*>(qkvbase + i1 * 288 + h * 24);
        #pragma unroll
        for (int u = 0; u < 6; u++) {
            float4 f = sq0[u];
            q2[2*u]      = pk2(f.x, f.y); q2[2*u+1]    = pk2(f.z, f.w);
            float4 g = sq1[u];
            q2[12+2*u]   = pk2(g.x, g.y); q2[12+2*u+1] = pk2(g.z, g.w);
        }
    }
    __syncthreads();

    const int ix = i0 & 7;
    const int iy0 = i0 >> 3;
    const int cx  = (wx == 7) ? ((ix < 4) ? 1 : 2) : 0;
    const int cnti0 = ((wy == 7) ? 1 : 0) * 3 + cx;
    const int cnti1 = ((wy == 7) ? 2 : 0) * 3 + cx;

    float sum0 = 0.f, sum1 = 0.f;
    ull_t o2a[12], o2b[12];
    #pragma unroll
    for (int u = 0; u < 12; u++) { o2a[u] = 0ull; o2b[u] = 0ull; }

    const float* kbp = ksm + h * 64 * 24;
    const float* vbp = vsm + h * 64 * 24;

    #pragma unroll 8
    for (int j = 0; j < 64; j++) {
        const ulonglong2* k4 = reinterpret_cast<const ulonglong2*>(kbp + j * 24);
        ull_t kr[12];
        {
            ulonglong2 t0 = k4[0], t1 = k4[1], t2 = k4[2];
            kr[0]=t0.x; kr[1]=t0.y; kr[2]=t1.x; kr[3]=t1.y; kr[4]=t2.x; kr[5]=t2.y;
            ulonglong2 t3 = k4[3], t4 = k4[4], t5 = k4[5];
            kr[6]=t3.x; kr[7]=t3.y; kr[8]=t4.x; kr[9]=t4.y; kr[10]=t5.x; kr[11]=t5.y;
        }
        ull_t aA = 0ull, aB = 0ull;
        #pragma unroll
        for (int u = 0; u < 12; u++) {
            fma2(aA, q2[u],      kr[u]);
            fma2(aB, q2[12 + u], kr[u]);
        }
        int jy = j >> 3, jx = j & 7;
        int bidx = ((iy0 - jy + 7) * 15 + (ix - jx + 7)) * 4 + h;
        float bias0 = bsm[bidx];
        float bias1 = bsm[bidx + 240];           // iy1 = iy0+4
        int cntj = ((wy == 7) ? ((jy < 4) ? 1 : 2) : 0) * 3
                 + ((wx == 7) ? ((jx < 4) ? 1 : 2) : 0);
        float m0 = (cnti0 != cntj) ? -100.f : 0.f;
        float m1 = (cnti1 != cntj) ? -100.f : 0.f;
        float lo, hi;
        up2(aA, lo, hi); float e0 = __expf(lo + hi + bias0 + m0);
        up2(aB, lo, hi); float e1 = __expf(lo + hi + bias1 + m1);
        sum0 += e0; sum1 += e1;
        ull_t p0 = pk2(e0, e0), p1 = pk2(e1, e1);

        const ulonglong2* v4 = reinterpret_cast<const ulonglong2*>(vbp + j * 24);
        ull_t vr[12];
        {
            ulonglong2 t0 = v4[0], t1 = v4[1], t2 = v4[2];
            vr[0]=t0.x; vr[1]=t0.y; vr[2]=t1.x; vr[3]=t1.y; vr[4]=t2.x; vr[5]=t2.y;
            ulonglong2 t3 = v4[3], t4 = v4[4], t5 = v4[5];
            vr[6]=t3.x; vr[7]=t3.y; vr[8]=t4.x; vr[9]=t4.y; vr[10]=t5.x; vr[11]=t5.y;
        }
        #pragma unroll
        for (int u = 0; u < 12; u++) {
            fma2(o2a[u], p0, vr[u]);
            fma2(o2b[u], p1, vr[u]);
        }
    }
    float inv0 = 1.f / sum0, inv1 = 1.f / sum1;
    #pragma unroll
    for (int u = 0; u < 12; u++) {
        float lo, hi;
        up2(o2a[u], lo, hi);
        aot[(h * 24 + 2 * u)     * 64 + i0] = lo * inv0;
        aot[(h * 24 + 2 * u + 1) * 64 + i0] = hi * inv0;
        up2(o2b[u], lo, hi);
        aot[(h * 24 + 2 * u)     * 64 + i1] = lo * inv1;
        aot[(h * 24 + 2 * u + 1) * 64 + i1] = hi * inv1;
    }
    __syncthreads();

    // ---- proj: 128 threads; tile = 16 tokens x 3 outs ----
    const int tg = tid >> 5, oo = lane;
    ull_t pa[8][3];
    #pragma unroll
    for (int u = 0; u < 8; u++)
        #pragma unroll
        for (int p = 0; p < 3; p++) pa[u][p] = 0ull;

    #pragma unroll 8
    for (int k = 0; k < 96; k++) {
        const ulonglong2* ap = reinterpret_cast<const ulonglong2*>(
            aot + k * 64 + (tg << 4));
        ulonglong2 A0 = ap[0], A1 = ap[1], A2 = ap[2], A3 = ap[3];
        ull_t a[8] = {A0.x, A0.y, A1.x, A1.y, A2.x, A2.y, A3.x, A3.y};
        const float* wp = pws + oo * 97 + k;
        #pragma unroll
        for (int p = 0; p < 3; p++) {
            float wv = wp[p * 3104];
            ull_t wpk = pk2(wv, wv);
            #pragma unroll
            for (int u = 0; u < 8; u++) fma2(pa[u][p], a[u], wpk);
        }
    }
    #pragma unroll
    for (int u = 0; u < 8; u++) {
        int t0 = (tg << 4) + 2 * u;
        #pragma unroll
        for (int dt = 0; dt < 2; dt++) {
            int t = t0 + dt;
            int ty = t >> 3, tx = t & 7;
            int y0 = ((wy << 3) + ty + 4) & 63;
            int x0 = ((wx << 3) + tx + 4) & 63;
            size_t row = ((size_t)((b << 12) + (y0 << 6) + x0)) * 96;
            #pragma unroll
            for (int p = 0; p < 3; p++) {
                int o = (p << 5) + oo;
                float lo, hi; up2(pa[u][p], lo, hi);
                g_x2[row + o] = x[row + o] + (dt ? hi : lo) + pb[o];
            }
        }
    }
}

// =============================================================================
// K3: LN2 + fc1 + exact GELU + fc2 + residual -> out  (wmma bf16, bf16 weights)
// 256 thr / 8 warps; CTA = 128 tokens (grid 2048). smem 109056 B.
// __launch_bounds__(256,2): cap regs at 128 so 2 CTAs/SM co-reside.
// =============================================================================
__global__ void __launch_bounds__(256, 2) k3_mlp_tc(
    const float* __restrict__ g2, const float* __restrict__ b2,
    const float* __restrict__ fb1, const float* __restrict__ fb2,
    float* __restrict__ out)
{
    extern __shared__ char smraw[];
    __nv_bfloat16* A   = reinterpret_cast<__nv_bfloat16*>(smraw);           // [128][104]
    float*         C1  = reinterpret_cast<float*>(smraw + 26624);           // [128][72]
    __nv_bfloat16* A2  = reinterpret_cast<__nv_bfloat16*>(smraw + 63488);   // [128][72]
    __nv_bfloat16* W1c = reinterpret_cast<__nv_bfloat16*>(smraw + 81920);   // [64][104]
    __nv_bfloat16* W2c = reinterpret_cast<__nv_bfloat16*>(smraw + 95232);   // [96][72]
    float*         C2s = reinterpret_cast<float*>(smraw);                   // [128][104] (reuse)

    const int tid = threadIdx.x;
    const int warp = tid >> 5;
    const size_t base = (size_t)blockIdx.x * 128 * 96;

    {   // ---- LN2 -> bf16 A ----
        int t = tid >> 1, part = tid & 1;
        const float4* src = reinterpret_cast<const float4*>(
            g_x2 + base + (size_t)t * 96 + part * 48);
        float v[48]; float s = 0.f, s2 = 0.f;
        #pragma unroll
        for (int i = 0; i < 12; i++) {
            float4 f = src[i];
            v[4*i] = f.x; v[4*i+1] = f.y; v[4*i+2] = f.z; v[4*i+3] = f.w;
        }
        #pragma unroll
        for (int i = 0; i < 48; i++) { s += v[i]; s2 += v[i] * v[i]; }
        s  += __shfl_xor_sync(0xffffffffu, s, 1);
        s2 += __shfl_xor_sync(0xffffffffu, s2, 1);
        float mu   = s * (1.f / 96.f);
        float rstd = rsqrtf(s2 * (1.f / 96.f) - mu * mu + 1e-5f);
        #pragma unroll
        for (int i = 0; i < 48; i++) {
            int c = part * 48 + i;
            A[t * 104 + c] = __float2bfloat16((v[i] - mu) * rstd * g2[c] + b2[c]);
        }
    }

    wmma::fragment<wmma::accumulator, 16, 16, 16, float> c2f[6];
    #pragma unroll
    for (int nn = 0; nn < 6; nn++) wmma::fill_fragment(c2f[nn], 0.f);

    uint32* W1u = reinterpret_cast<uint32*>(W1c);
    uint32* W2u = reinterpret_cast<uint32*>(W2c);
    const uint32* w1h_u = reinterpret_cast<const uint32*>(g_w1h);
    const uint32* w2h_u = reinterpret_cast<const uint32*>(g_w2h);

    for (int nch = 0; nch < 6; nch++) {
        __syncthreads();
        for (int idx = tid; idx < 3072; idx += 256) {        // w1 chunk [64][96]
            int nl = idx / 48, kp = idx - nl * 48;
            W1u[nl * 52 + kp] = w1h_u[(nch * 64 + nl) * 48 + kp];
        }
        for (int idx = tid; idx < 3072; idx += 256) {        // w2 chunk [96][64]
            int nl = idx >> 5, kp = idx & 31;
            W2u[nl * 36 + kp] = w2h_u[nl * 192 + nch * 32 + kp];
        }
        __syncthreads();

        // ---- fc1 ----
        wmma::fragment<wmma::accumulator, 16, 16, 16, float> c1f[4];
        #pragma unroll
        for (int nn = 0; nn < 4; nn++) wmma::fill_fragment(c1f[nn], 0.f);
        #pragma unroll
        for (int kk = 0; kk < 6; kk++) {
            wmma::fragment<wmma::matrix_a, 16, 16, 16, __nv_bfloat16, wmma::row_major> af;
            wmma::load_matrix_sync(af, A + warp * 16 * 104 + kk * 16, 104);
            #pragma unroll
            for (int nn = 0; nn < 4; nn++) {
                wmma::fragment<wmma::matrix_b, 16, 16, 16, __nv_bfloat16, wmma::col_major> bf;
                wmma::load_matrix_sync(bf, W1c + nn * 16 * 104 + kk * 16, 104);
                wmma::mma_sync(c1f[nn], af, bf, c1f[nn]);
            }
        }
        #pragma unroll
        for (int nn = 0; nn < 4; nn++)
            wmma::store_matrix_sync(C1 + warp * 16 * 72 + nn * 16, c1f[nn], 72,
                                    wmma::mem_row_major);
        __syncthreads();

        // ---- bias + exact GELU -> bf16 A2 ----
        for (int idx = tid; idx < 128 * 64; idx += 256) {
            int t = idx >> 6, c = idx & 63;
            float v = C1[t * 72 + c] + fb1[nch * 64 + c];
            v = 0.5f * v * (1.f + erff(v * 0.70710678118654752f));
            A2[t * 72 + c] = __float2bfloat16(v);
        }
        __syncthreads();

        // ---- fc2 partial ----
        #pragma unroll
        for (int kk = 0; kk < 4; kk++) {
            wmma::fragment<wmma::matrix_a, 16, 16, 16, __nv_bfloat16, wmma::row_major> a2f;
            wmma::load_matrix_sync(a2f, A2 + warp * 16 * 72 + kk * 16, 72);
            #pragma unroll
            for (int nn = 0; nn < 6; nn++) {
                wmma::fragment<wmma::matrix_b, 16, 16, 16, __nv_bfloat16, wmma::col_major> b2f;
                wmma::load_matrix_sync(b2f, W2c + nn * 16 * 72 + kk * 16, 72);
                wmma::mma_sync(c2f[nn], a2f, b2f, c2f[nn]);
            }
        }
    }
    __syncthreads();

    #pragma unroll
    for (int nn = 0; nn < 6; nn++)
        wmma::store_matrix_sync(C2s + warp * 16 * 104 + nn * 16, c2f[nn], 104,
                                wmma::mem_row_major);
    __syncthreads();
    for (int idx = tid; idx < 128 * 96; idx += 256) {
        int t = idx / 96, c = idx - t * 96;
        out[base + idx] = g_x2[base + idx] + C2s[t * 104 + c] + fb2[c];
    }
}

// =============================================================================
extern "C" void kernel_launch(void* const* d_in, const int* in_sizes, int n_in,
                              void* d_out, int out_size)
{
    (void)in_sizes; (void)n_in; (void)out_size;
    const float* x   = (const float*)d_in[0];
    const float* n1g = (const float*)d_in[1];
    const float* n1b = (const float*)d_in[2];
    const float* qw  = (const float*)d_in[3];
    const float* qb  = (const float*)d_in[4];
    const float* bt  = (const float*)d_in[5];
    const float* pw  = (const float*)d_in[6];
    const float* pb  = (const float*)d_in[7];
    const float* n2g = (const float*)d_in[8];
    const float* n2b = (const float*)d_in[9];
    const float* w1  = (const float*)d_in[10];
    const float* fb1 = (const float*)d_in[11];
    const float* w2  = (const float*)d_in[12];
    const float* fb2 = (const float*)d_in[13];
    float* out = (float*)d_out;

    cudaFuncSetAttribute(k1_ln_qkv_tc, cudaFuncAttributeMaxDynamicSharedMemorySize,  99840);
    cudaFuncSetAttribute(k2_attn_proj, cudaFuncAttributeMaxDynamicSharedMemorySize, 114576);
    cudaFuncSetAttribute(k3_mlp_tc,    cudaFuncAttributeMaxDynamicSharedMemorySize, 109056);

    k0_cvt_weights<<<144, 256>>>(qw, w1, w2);
    k1_ln_qkv_tc<<<2048, 256,  99840>>>(x, n1g, n1b, qb);
    k2_attn_proj<<<4096, 128, 114576>>>(x, bt, pw, pb);
    k3_mlp_tc   <<<2048, 256, 109056>>>(n2g, n2b, fb1, fb2, out);
}